// round 3
// baseline (speedup 1.0000x reference)
#include <cuda_runtime.h>
#include <math.h>
#include <stdint.h>

#define D   10112
#define H   2048
#define P   62
#define NB  62
#define NBP (NB*P)     // 3844
#define DCH 79         // D / 128

// ---------------- scratch (device globals; no allocation) ----------------
__device__ float g_bigpart[3 * DCH * H];   // split-K partials for the 3 big matvecs
__device__ float g_h1[H];                  // bass hidden1 (post-selu)
__device__ float g_ua0[H];                 // alto  x@aw1[:D] + ab1 (pre-selu, shared part)
__device__ float g_ut0[H];                 // tenor x@tw1[:D] + tb1
__device__ float g_p2[16 * H];             // bass layer2 partials
__device__ float g_h2[H];                  // bass hidden2
__device__ float g_lbp[32 * 64];           // bass layer3 partials
__device__ float g_logb[64];               // bass logits
__device__ float g_probs1[NB];             // bass probs sorted desc
__device__ int   g_pitch1[NB];             // bass pitches sorted by prob
__device__ float g_hX1[NB * H];            // stage hidden1 (62 x 2048)
__device__ float g_gpart[8 * 64 * H];      // GEMM split-K partials
__device__ float g_hX2[NB * H];            // stage hidden2
__device__ float g_logits[NBP];            // stage logits 62x62
__device__ float g_flat[NBP];              // softmax*prob flattened
__device__ float g_probs2[NB];
__device__ int   g_pb2[NB];
__device__ int   g_pa2[NB];

__device__ __forceinline__ float selu_f(float x) {
    const float sc = 1.0507009873554805f;
    const float al = 1.6732632423543772f;
    return x > 0.f ? sc * x : sc * al * expm1f(x);
}

// ---------------- kernel 1: the three big D->H matvecs, split-K ----------
// grid (H/512, 79, 3), block 128. Each thread owns 4 consecutive output cols
// (float4). W row-major (rows, H); we use first D rows.
__global__ __launch_bounds__(128) void big_matvec(const float* __restrict__ x,
                           const float* __restrict__ W0,
                           const float* __restrict__ W1,
                           const float* __restrict__ W2) {
    __shared__ float sx[128];
    int t = threadIdx.x;
    int j4 = blockIdx.x * 128 + t;          // float4 column index
    int c = blockIdx.y;
    int z = blockIdx.z;
    const float* __restrict__ W = (z == 0) ? W0 : ((z == 1) ? W1 : W2);
    int i0 = c * 128;
    sx[t] = x[i0 + t];
    __syncthreads();
    const float4* __restrict__ W4 = (const float4*)W;
    float4 acc = make_float4(0.f, 0.f, 0.f, 0.f);
#pragma unroll 8
    for (int i = 0; i < 128; ++i) {
        float xv = sx[i];
        float4 w = W4[(size_t)(i0 + i) * (H / 4) + j4];
        acc.x += xv * w.x; acc.y += xv * w.y; acc.z += xv * w.z; acc.w += xv * w.w;
    }
    ((float4*)g_bigpart)[((size_t)z * DCH + c) * (H / 4) + j4] = acc;
}

// grid (H/512, 3), block 128 (each thread: 4 consecutive cols)
__global__ __launch_bounds__(128) void big_reduce(const float* __restrict__ bb1,
                           const float* __restrict__ ab1,
                           const float* __restrict__ tb1) {
    int j4 = blockIdx.x * 128 + threadIdx.x;
    int z = blockIdx.y;
    const float4* __restrict__ bp4 = (const float4*)g_bigpart;
    float4 s = make_float4(0.f, 0.f, 0.f, 0.f);
#pragma unroll 4
    for (int c = 0; c < DCH; ++c) {
        float4 v = bp4[((size_t)z * DCH + c) * (H / 4) + j4];
        s.x += v.x; s.y += v.y; s.z += v.z; s.w += v.w;
    }
    if (z == 0) {
        float4 b = ((const float4*)bb1)[j4];
        float4 o;
        o.x = selu_f(s.x + b.x); o.y = selu_f(s.y + b.y);
        o.z = selu_f(s.z + b.z); o.w = selu_f(s.w + b.w);
        ((float4*)g_h1)[j4] = o;
    } else if (z == 1) {
        float4 b = ((const float4*)ab1)[j4];
        float4 o = make_float4(s.x + b.x, s.y + b.y, s.z + b.z, s.w + b.w);
        ((float4*)g_ua0)[j4] = o;
    } else {
        float4 b = ((const float4*)tb1)[j4];
        float4 o = make_float4(s.x + b.x, s.y + b.y, s.z + b.z, s.w + b.w);
        ((float4*)g_ut0)[j4] = o;
    }
}

// ---------------- bass layer2: 2048->2048 matvec, split-K ---------------
// grid (H/512, 16), block 128; each thread 4 cols (float4)
__global__ __launch_bounds__(128) void l2_part(const float* __restrict__ W) {
    __shared__ float sx[128];
    int t = threadIdx.x;
    int j4 = blockIdx.x * 128 + t;
    int c = blockIdx.y;
    int i0 = c * 128;
    sx[t] = g_h1[i0 + t];
    __syncthreads();
    const float4* __restrict__ W4 = (const float4*)W;
    float4 acc = make_float4(0.f, 0.f, 0.f, 0.f);
#pragma unroll 8
    for (int i = 0; i < 128; ++i) {
        float xv = sx[i];
        float4 w = W4[(size_t)(i0 + i) * (H / 4) + j4];
        acc.x += xv * w.x; acc.y += xv * w.y; acc.z += xv * w.z; acc.w += xv * w.w;
    }
    ((float4*)g_p2)[(size_t)c * (H / 4) + j4] = acc;
}

// grid H/512, block 128
__global__ __launch_bounds__(128) void l2_reduce(const float* __restrict__ b) {
    int j4 = blockIdx.x * 128 + threadIdx.x;
    const float4* __restrict__ p4 = (const float4*)g_p2;
    float4 s = make_float4(0.f, 0.f, 0.f, 0.f);
#pragma unroll
    for (int c = 0; c < 16; ++c) {
        float4 v = p4[(size_t)c * (H / 4) + j4];
        s.x += v.x; s.y += v.y; s.z += v.z; s.w += v.w;
    }
    float4 bb = ((const float4*)b)[j4];
    float4 o;
    o.x = selu_f(s.x + bb.x); o.y = selu_f(s.y + bb.y);
    o.z = selu_f(s.z + bb.z); o.w = selu_f(s.w + bb.w);
    ((float4*)g_h2)[j4] = o;
}

// ---------------- bass layer3: 2048->62 ----------------------------------
// grid 32, block 64 : block c handles k in [64c, 64c+64)
__global__ __launch_bounds__(64) void bass_l3_part(const float* __restrict__ W3) {
    int n = threadIdx.x;
    int k0 = blockIdx.x * 64;
    float acc = 0.f;
    if (n < P) {
#pragma unroll 8
        for (int k = k0; k < k0 + 64; ++k) acc += g_h2[k] * W3[k * P + n];
    }
    g_lbp[blockIdx.x * 64 + n] = acc;
}

// grid 1, block 64
__global__ __launch_bounds__(64) void bass_l3_reduce(const float* __restrict__ b3) {
    int n = threadIdx.x;
    if (n >= P) return;
    float s = 0.f;
#pragma unroll
    for (int c = 0; c < 32; ++c) s += g_lbp[c * 64 + n];
    g_logb[n] = s + b3[n];
}

// ---------------- bass softmax + full descending sort (62) ---------------
// grid 1, block 64
__global__ __launch_bounds__(64) void bass_softsort() {
    __shared__ float pv[64];
    __shared__ float red;
    int t = threadIdx.x;
    float v = (t < P) ? g_logb[t] : -1e30f;
    pv[t] = v;
    __syncthreads();
    if (t == 0) { float mx = -1e30f; for (int i = 0; i < P; ++i) mx = fmaxf(mx, pv[i]); red = mx; }
    __syncthreads();
    float e = (t < P) ? expf(v - red) : 0.f;
    pv[t] = e;
    __syncthreads();
    if (t == 0) { float s = 0.f; for (int i = 0; i < P; ++i) s += pv[i]; red = s; }
    __syncthreads();
    float p = e / red;
    pv[t] = (t < P) ? p : -1.f;
    __syncthreads();
    if (t < P) {
        int r = 0;
        for (int i = 0; i < P; ++i) {
            float o = pv[i];
            r += (o > p) || (o == p && i < t);
        }
        g_probs1[r] = p;
        g_pitch1[r] = t;
    }
}

// ---------------- stage hidden1 via row-gather + selu --------------------
// grid (H/512, 62), block 128, float4. stage 0: alto (one row), 1: tenor (two)
__global__ __launch_bounds__(128) void hidden1(int stage, const float* __restrict__ W1) {
    int j4 = blockIdx.x * 128 + threadIdx.x;
    int i = blockIdx.y;
    const float4* __restrict__ W4 = (const float4*)W1;
    float4 o;
    if (stage == 0) {
        int pb = g_pitch1[i];
        float4 u = ((const float4*)g_ua0)[j4];
        float4 w = W4[(size_t)(D + pb) * (H / 4) + j4];
        o = make_float4(u.x + w.x, u.y + w.y, u.z + w.z, u.w + w.w);
    } else {
        int pb = g_pb2[i];
        int pa = g_pa2[i];
        float4 u = ((const float4*)g_ut0)[j4];
        float4 wb = W4[(size_t)(D + pb) * (H / 4) + j4];
        float4 wa = W4[(size_t)(D + P + pa) * (H / 4) + j4];
        o = make_float4(u.x + wb.x + wa.x, u.y + wb.y + wa.y,
                        u.z + wb.z + wa.z, u.w + wb.w + wa.w);
    }
    float4 r;
    r.x = selu_f(o.x); r.y = selu_f(o.y); r.z = selu_f(o.z); r.w = selu_f(o.w);
    ((float4*)g_hX1)[(size_t)i * (H / 4) + j4] = r;
}

// ---------------- stage layer2 GEMM: (62x2048) @ (2048x2048), split-K ----
// grid (32 n-tiles, 8 k-chunks), block 256. Partial -> g_gpart.
#define GM  64
#define GN  64
#define GKT 32
#define KCH 8
#define KLEN (H / KCH)   // 256
__global__ __launch_bounds__(256) void gemm_part(const float* __restrict__ B) {
    __shared__ float sA[GKT][GM + 1];
    __shared__ float sB[GKT][GN];
    int t = threadIdx.x;
    int n0 = blockIdx.x * GN;
    int kc = blockIdx.y;
    int kbase = kc * KLEN;
    int tx = t & 15, ty = t >> 4;
    float acc[4][4] = {};
    for (int kt = 0; kt < KLEN; kt += GKT) {
        int k0 = kbase + kt;
#pragma unroll
        for (int r = 0; r < 8; ++r) {
            int idx = t + r * 256;
            int kk = idx & 31, mm = idx >> 5;
            sA[kk][mm] = (mm < NB) ? g_hX1[mm * H + k0 + kk] : 0.f;
        }
#pragma unroll
        for (int r = 0; r < 8; ++r) {
            int idx = t + r * 256;
            int nn = idx & 63, kk = idx >> 6;
            sB[kk][nn] = B[(size_t)(k0 + kk) * H + n0 + nn];
        }
        __syncthreads();
#pragma unroll
        for (int k = 0; k < GKT; ++k) {
            float a[4], b[4];
#pragma unroll
            for (int r = 0; r < 4; ++r) a[r] = sA[k][ty * 4 + r];
#pragma unroll
            for (int c = 0; c < 4; ++c) b[c] = sB[k][tx * 4 + c];
#pragma unroll
            for (int r = 0; r < 4; ++r)
#pragma unroll
                for (int c = 0; c < 4; ++c) acc[r][c] += a[r] * b[c];
        }
        __syncthreads();
    }
#pragma unroll
    for (int r = 0; r < 4; ++r) {
        int m = ty * 4 + r;
#pragma unroll
        for (int c = 0; c < 4; ++c) {
            g_gpart[((size_t)kc * GM + m) * H + n0 + tx * 4 + c] = acc[r][c];
        }
    }
}

// grid (62*2048/4)/256 = 124, block 256, float4
__global__ __launch_bounds__(256) void gemm_reduce(const float* __restrict__ bias) {
    int idx4 = blockIdx.x * 256 + threadIdx.x;          // float4 index into 62x2048
    if (idx4 >= NB * H / 4) return;
    int m = idx4 / (H / 4), n4 = idx4 % (H / 4);
    const float4* __restrict__ gp4 = (const float4*)g_gpart;
    float4 s = make_float4(0.f, 0.f, 0.f, 0.f);
#pragma unroll
    for (int kc = 0; kc < KCH; ++kc) {
        float4 v = gp4[((size_t)kc * GM + m) * (H / 4) + n4];
        s.x += v.x; s.y += v.y; s.z += v.z; s.w += v.w;
    }
    float4 b = ((const float4*)bias)[n4];
    float4 o;
    o.x = selu_f(s.x + b.x); o.y = selu_f(s.y + b.y);
    o.z = selu_f(s.z + b.z); o.w = selu_f(s.w + b.w);
    ((float4*)g_hX2)[idx4] = o;
}

// ---------------- stage layer3: (62x2048) @ (2048x62) --------------------
// grid 62, block 512 (= 8 k-segments x 64 n)
__global__ __launch_bounds__(512) void l3_kernel(const float* __restrict__ W3, const float* __restrict__ b3) {
    __shared__ float sh[H];
    __shared__ float sred[8 * 64];
    int m = blockIdx.x;
    int t = threadIdx.x;
    for (int k = t; k < H; k += 512) sh[k] = g_hX2[m * H + k];
    __syncthreads();
    int n = t & 63, seg = t >> 6;
    float acc = 0.f;
    if (n < P) {
        int k0 = seg * 256;
#pragma unroll 4
        for (int k = k0; k < k0 + 256; ++k) acc += sh[k] * W3[k * P + n];
    }
    sred[t] = acc;
    __syncthreads();
    if (seg == 0 && n < P) {
        float s = 0.f;
#pragma unroll
        for (int q = 0; q < 8; ++q) s += sred[q * 64 + n];
        g_logits[m * P + n] = s + b3[n];
    }
}

// ---------------- stage row softmax * carry-prob -------------------------
// grid 62, block 64
__global__ __launch_bounds__(64) void softscale(int stage) {
    __shared__ float vals[64];
    __shared__ float red;
    int m = blockIdx.x, t = threadIdx.x;
    float v = (t < P) ? g_logits[m * P + t] : -1e30f;
    vals[t] = v;
    __syncthreads();
    if (t == 0) { float mx = -1e30f; for (int i = 0; i < P; ++i) mx = fmaxf(mx, vals[i]); red = mx; }
    __syncthreads();
    float e = (t < P) ? expf(v - red) : 0.f;
    vals[t] = e;
    __syncthreads();
    if (t == 0) { float s = 0.f; for (int i = 0; i < P; ++i) s += vals[i]; red = s; }
    __syncthreads();
    float scale = (stage == 0) ? g_probs1[m] : g_probs2[m];
    if (t < P) g_flat[m * P + t] = (e / red) * scale;
}

// ---------------- exact top-62 of 3844 by rank count ---------------------
// grid 16, block 256. Rank = #{i : v_i > v_g  or (v_i == v_g and i < g)}
__global__ __launch_bounds__(256) void topk62(int stage, float* __restrict__ out) {
    __shared__ float sv[NBP];   // 3844 floats = 15.4 KB
    int t = threadIdx.x;
    for (int i = t; i < NBP; i += 256) sv[i] = g_flat[i];
    __syncthreads();
    int g = blockIdx.x * 256 + t;
    if (g >= NBP) return;
    float v = sv[g];
    int r = 0;
    const float4* sv4 = (const float4*)sv;   // 3844 = 961 * 4
#pragma unroll 4
    for (int q = 0; q < NBP / 4; ++q) {
        float4 o = sv4[q];
        int base = q * 4;
        r += (o.x > v) || (o.x == v && (base + 0) < g);
        r += (o.y > v) || (o.y == v && (base + 1) < g);
        r += (o.z > v) || (o.z == v && (base + 2) < g);
        r += (o.w > v) || (o.w == v && (base + 3) < g);
    }
    if (r < NB) {
        int row = g / P, col = g % P;
        if (stage == 0) {
            g_probs2[r] = v;
            g_pb2[r] = g_pitch1[row];
            g_pa2[r] = col;
        } else {
            out[r * 4 + 0] = v;
            out[r * 4 + 1] = (float)g_pb2[row];
            out[r * 4 + 2] = (float)g_pa2[row];
            out[r * 4 + 3] = (float)col;
        }
    }
}

// ---------------- launch ---------------------------------------------------
extern "C" void kernel_launch(void* const* d_in, const int* in_sizes, int n_in,
                              void* d_out, int out_size) {
    (void)in_sizes; (void)n_in; (void)out_size;
    const float* x   = (const float*)d_in[0];
    const float* bw1 = (const float*)d_in[1];
    const float* bb1 = (const float*)d_in[2];
    const float* bw2 = (const float*)d_in[3];
    const float* bb2 = (const float*)d_in[4];
    const float* bw3 = (const float*)d_in[5];
    const float* bb3 = (const float*)d_in[6];
    const float* aw1 = (const float*)d_in[7];
    const float* ab1 = (const float*)d_in[8];
    const float* aw2 = (const float*)d_in[9];
    const float* ab2 = (const float*)d_in[10];
    const float* aw3 = (const float*)d_in[11];
    const float* ab3 = (const float*)d_in[12];
    const float* tw1 = (const float*)d_in[13];
    const float* tb1 = (const float*)d_in[14];
    const float* tw2 = (const float*)d_in[15];
    const float* tb2 = (const float*)d_in[16];
    const float* tw3 = (const float*)d_in[17];
    const float* tb3 = (const float*)d_in[18];
    float* out = (float*)d_out;

    // 3 big matvecs (bass L1 + shared parts of alto/tenor L1) in one pass
    big_matvec<<<dim3(H / 512, DCH, 3), 128>>>(x, bw1, aw1, tw1);
    big_reduce<<<dim3(H / 512, 3), 128>>>(bb1, ab1, tb1);

    // bass trunk
    l2_part<<<dim3(H / 512, 16), 128>>>(bw2);
    l2_reduce<<<H / 512, 128>>>(bb2);
    bass_l3_part<<<32, 64>>>(bw3);
    bass_l3_reduce<<<1, 64>>>(bb3);
    bass_softsort<<<1, 64>>>();

    // alto stage
    hidden1<<<dim3(H / 512, NB), 128>>>(0, aw1);
    gemm_part<<<dim3(32, KCH), 256>>>(aw2);
    gemm_reduce<<<(NB * H / 4 + 255) / 256, 256>>>(ab2);
    l3_kernel<<<NB, 512>>>(aw3, ab3);
    softscale<<<NB, 64>>>(0);
    topk62<<<16, 256>>>(0, out);

    // tenor stage
    hidden1<<<dim3(H / 512, NB), 128>>>(1, tw1);
    gemm_part<<<dim3(32, KCH), 256>>>(tw2);
    gemm_reduce<<<(NB * H / 4 + 255) / 256, 256>>>(tb2);
    l3_kernel<<<NB, 512>>>(tw3, tb3);
    softscale<<<NB, 64>>>(1);
    topk62<<<16, 256>>>(1, out);
}

// round 4
// speedup vs baseline: 1.6897x; 1.6897x over previous
#include <cuda_runtime.h>
#include <math.h>
#include <stdint.h>

#define D   10112
#define H   2048
#define P   62
#define NB  62
#define NBP (NB*P)     // 3844
#define DCH 79         // D / 128

// ---------------- scratch (device globals; no allocation) ----------------
__device__ float g_bigpart[3 * DCH * H];   // split-K partials for the 3 big matvecs
__device__ float g_h1[H];                  // bass hidden1 (post-selu)
__device__ float g_ua0[H];                 // alto  x@aw1[:D] + ab1 (pre-selu, shared part)
__device__ float g_ut0[H];                 // tenor x@tw1[:D] + tb1
__device__ float g_p2[64 * H];             // bass layer2 partials (64 k-chunks)
__device__ float g_h2[H];                  // bass hidden2
__device__ float g_lbp[32 * 64];           // bass layer3 partials
__device__ float g_probs1[NB];             // bass probs sorted desc
__device__ int   g_pitch1[NB];             // bass pitches sorted by prob
__device__ float g_hX1[NB * H];            // stage hidden1 (62 x 2048)
__device__ float g_gpart[8 * 64 * H];      // GEMM split-K partials
__device__ float g_hX2[NB * H];            // stage hidden2
__device__ float g_l3p[62 * 32 * 64];      // stage L3 partials
__device__ float g_flat[NBP];              // softmax*prob flattened
__device__ float g_probs2[NB];
__device__ int   g_pb2[NB];
__device__ int   g_pa2[NB];

__device__ __forceinline__ float selu_f(float x) {
    const float sc = 1.0507009873554805f;
    const float al = 1.6732632423543772f;
    return x > 0.f ? sc * x : sc * al * expm1f(x);
}

// ---------------- kernel 1: the three big D->H matvecs, split-K ----------
// grid (H/512, 79, 3), block 128. Each thread owns 4 consecutive output cols.
__global__ __launch_bounds__(128, 8) void big_matvec(const float* __restrict__ x,
                           const float* __restrict__ W0,
                           const float* __restrict__ W1,
                           const float* __restrict__ W2) {
    __shared__ float sx[128];
    int t = threadIdx.x;
    int j4 = blockIdx.x * 128 + t;          // float4 column index
    int c = blockIdx.y;
    int z = blockIdx.z;
    const float* __restrict__ W = (z == 0) ? W0 : ((z == 1) ? W1 : W2);
    int i0 = c * 128;
    sx[t] = x[i0 + t];
    __syncthreads();
    const float4* __restrict__ W4 = (const float4*)W;
    float4 acc = make_float4(0.f, 0.f, 0.f, 0.f);
#pragma unroll 8
    for (int i = 0; i < 128; ++i) {
        float xv = sx[i];
        float4 w = W4[(size_t)(i0 + i) * (H / 4) + j4];
        acc.x += xv * w.x; acc.y += xv * w.y; acc.z += xv * w.z; acc.w += xv * w.w;
    }
    ((float4*)g_bigpart)[((size_t)z * DCH + c) * (H / 4) + j4] = acc;
}

// grid (H/512, 3), block 512 = 128 float4-cols x 4 chunk-groups (20/20/20/19)
__global__ __launch_bounds__(512) void big_reduce(const float* __restrict__ bb1,
                           const float* __restrict__ ab1,
                           const float* __restrict__ tb1) {
    __shared__ float4 sred[4][128];
    int t = threadIdx.x;
    int col = t & 127;
    int grp = t >> 7;
    int j4 = blockIdx.x * 128 + col;
    int z = blockIdx.y;
    const float4* __restrict__ bp4 = (const float4*)g_bigpart;
    int c0 = grp * 20;
    int cn = (grp == 3) ? 19 : 20;
    float4 s = make_float4(0.f, 0.f, 0.f, 0.f);
#pragma unroll 5
    for (int c = 0; c < cn; ++c) {
        float4 v = bp4[((size_t)z * DCH + c0 + c) * (H / 4) + j4];
        s.x += v.x; s.y += v.y; s.z += v.z; s.w += v.w;
    }
    sred[grp][col] = s;
    __syncthreads();
    if (grp == 0) {
        float4 a = sred[0][col], b = sred[1][col], c = sred[2][col], d = sred[3][col];
        // fixed order: ((g0+g1)+g2)+g3
        float4 sm = make_float4(((a.x + b.x) + c.x) + d.x, ((a.y + b.y) + c.y) + d.y,
                                ((a.z + b.z) + c.z) + d.z, ((a.w + b.w) + c.w) + d.w);
        if (z == 0) {
            float4 bb = ((const float4*)bb1)[j4];
            float4 o;
            o.x = selu_f(sm.x + bb.x); o.y = selu_f(sm.y + bb.y);
            o.z = selu_f(sm.z + bb.z); o.w = selu_f(sm.w + bb.w);
            ((float4*)g_h1)[j4] = o;
        } else if (z == 1) {
            float4 bb = ((const float4*)ab1)[j4];
            ((float4*)g_ua0)[j4] = make_float4(sm.x + bb.x, sm.y + bb.y, sm.z + bb.z, sm.w + bb.w);
        } else {
            float4 bb = ((const float4*)tb1)[j4];
            ((float4*)g_ut0)[j4] = make_float4(sm.x + bb.x, sm.y + bb.y, sm.z + bb.z, sm.w + bb.w);
        }
    }
}

// ---------------- bass layer2: 2048->2048 matvec, split-K (chunk 32) -----
// grid (H/512, 64), block 128
__global__ __launch_bounds__(128, 8) void l2_part(const float* __restrict__ W) {
    __shared__ float sx[32];
    int t = threadIdx.x;
    int j4 = blockIdx.x * 128 + t;
    int c = blockIdx.y;
    int i0 = c * 32;
    if (t < 32) sx[t] = g_h1[i0 + t];
    __syncthreads();
    const float4* __restrict__ W4 = (const float4*)W;
    float4 acc = make_float4(0.f, 0.f, 0.f, 0.f);
#pragma unroll 8
    for (int i = 0; i < 32; ++i) {
        float xv = sx[i];
        float4 w = W4[(size_t)(i0 + i) * (H / 4) + j4];
        acc.x += xv * w.x; acc.y += xv * w.y; acc.z += xv * w.z; acc.w += xv * w.w;
    }
    ((float4*)g_p2)[(size_t)c * (H / 4) + j4] = acc;
}

// grid H/512, block 512 = 128 cols x 4 groups of 16 chunks
__global__ __launch_bounds__(512) void l2_reduce(const float* __restrict__ b) {
    __shared__ float4 sred[4][128];
    int t = threadIdx.x;
    int col = t & 127;
    int grp = t >> 7;
    int j4 = blockIdx.x * 128 + col;
    const float4* __restrict__ p4 = (const float4*)g_p2;
    float4 s = make_float4(0.f, 0.f, 0.f, 0.f);
#pragma unroll
    for (int c = 0; c < 16; ++c) {
        float4 v = p4[(size_t)(grp * 16 + c) * (H / 4) + j4];
        s.x += v.x; s.y += v.y; s.z += v.z; s.w += v.w;
    }
    sred[grp][col] = s;
    __syncthreads();
    if (grp == 0) {
        float4 a = sred[0][col], bb = sred[1][col], c = sred[2][col], d = sred[3][col];
        float4 sm = make_float4(((a.x + bb.x) + c.x) + d.x, ((a.y + bb.y) + c.y) + d.y,
                                ((a.z + bb.z) + c.z) + d.z, ((a.w + bb.w) + c.w) + d.w);
        float4 bv = ((const float4*)b)[j4];
        float4 o;
        o.x = selu_f(sm.x + bv.x); o.y = selu_f(sm.y + bv.y);
        o.z = selu_f(sm.z + bv.z); o.w = selu_f(sm.w + bv.w);
        ((float4*)g_h2)[j4] = o;
    }
}

// ---------------- bass layer3: 2048->62 ----------------------------------
// grid 32, block 64 : block c handles k in [64c, 64c+64)
__global__ __launch_bounds__(64) void bass_l3_part(const float* __restrict__ W3) {
    int n = threadIdx.x;
    int k0 = blockIdx.x * 64;
    float acc = 0.f;
    if (n < P) {
#pragma unroll 8
        for (int k = k0; k < k0 + 64; ++k) acc += g_h2[k] * W3[k * P + n];
    }
    g_lbp[blockIdx.x * 64 + n] = acc;
}

// fused: reduce partials + bias + softmax + descending sort. grid 1, block 64
__global__ __launch_bounds__(64) void bass_fused(const float* __restrict__ b3) {
    __shared__ float pv[64];
    __shared__ float red;
    int t = threadIdx.x;
    float s = 0.f;
#pragma unroll 8
    for (int c = 0; c < 32; ++c) s += g_lbp[c * 64 + t];
    float v = (t < P) ? (s + b3[t]) : -1e30f;
    pv[t] = v;
    __syncthreads();
    if (t == 0) { float mx = -1e30f; for (int i = 0; i < P; ++i) mx = fmaxf(mx, pv[i]); red = mx; }
    __syncthreads();
    float e = (t < P) ? expf(v - red) : 0.f;
    pv[t] = e;
    __syncthreads();
    if (t == 0) { float ss = 0.f; for (int i = 0; i < P; ++i) ss += pv[i]; red = ss; }
    __syncthreads();
    float p = e / red;
    pv[t] = (t < P) ? p : -1.f;
    __syncthreads();
    if (t < P) {
        int r = 0;
        for (int i = 0; i < P; ++i) {
            float o = pv[i];
            r += (o > p) || (o == p && i < t);
        }
        g_probs1[r] = p;
        g_pitch1[r] = t;
    }
}

// ---------------- stage hidden1 via row-gather + selu --------------------
// grid (H/512, 62), block 128, float4
__global__ __launch_bounds__(128) void hidden1(int stage, const float* __restrict__ W1) {
    int j4 = blockIdx.x * 128 + threadIdx.x;
    int i = blockIdx.y;
    const float4* __restrict__ W4 = (const float4*)W1;
    float4 o;
    if (stage == 0) {
        int pb = g_pitch1[i];
        float4 u = ((const float4*)g_ua0)[j4];
        float4 w = W4[(size_t)(D + pb) * (H / 4) + j4];
        o = make_float4(u.x + w.x, u.y + w.y, u.z + w.z, u.w + w.w);
    } else {
        int pb = g_pb2[i];
        int pa = g_pa2[i];
        float4 u = ((const float4*)g_ut0)[j4];
        float4 wb = W4[(size_t)(D + pb) * (H / 4) + j4];
        float4 wa = W4[(size_t)(D + P + pa) * (H / 4) + j4];
        o = make_float4(u.x + wb.x + wa.x, u.y + wb.y + wa.y,
                        u.z + wb.z + wa.z, u.w + wb.w + wa.w);
    }
    float4 r;
    r.x = selu_f(o.x); r.y = selu_f(o.y); r.z = selu_f(o.z); r.w = selu_f(o.w);
    ((float4*)g_hX1)[(size_t)i * (H / 4) + j4] = r;
}

// ---------------- stage layer2 GEMM: (62x2048) @ (2048x2048), split-K ----
#define GM  64
#define GN  64
#define GKT 32
#define KCH 8
#define KLEN (H / KCH)   // 256
__global__ __launch_bounds__(256) void gemm_part(const float* __restrict__ B) {
    __shared__ float sA[GKT][GM + 1];
    __shared__ float sB[GKT][GN];
    int t = threadIdx.x;
    int n0 = blockIdx.x * GN;
    int kc = blockIdx.y;
    int kbase = kc * KLEN;
    int tx = t & 15, ty = t >> 4;
    float acc[4][4] = {};
    for (int kt = 0; kt < KLEN; kt += GKT) {
        int k0 = kbase + kt;
#pragma unroll
        for (int r = 0; r < 8; ++r) {
            int idx = t + r * 256;
            int kk = idx & 31, mm = idx >> 5;
            sA[kk][mm] = (mm < NB) ? g_hX1[mm * H + k0 + kk] : 0.f;
        }
#pragma unroll
        for (int r = 0; r < 8; ++r) {
            int idx = t + r * 256;
            int nn = idx & 63, kk = idx >> 6;
            sB[kk][nn] = B[(size_t)(k0 + kk) * H + n0 + nn];
        }
        __syncthreads();
#pragma unroll
        for (int k = 0; k < GKT; ++k) {
            float a[4], b[4];
#pragma unroll
            for (int r = 0; r < 4; ++r) a[r] = sA[k][ty * 4 + r];
#pragma unroll
            for (int c = 0; c < 4; ++c) b[c] = sB[k][tx * 4 + c];
#pragma unroll
            for (int r = 0; r < 4; ++r)
#pragma unroll
                for (int c = 0; c < 4; ++c) acc[r][c] += a[r] * b[c];
        }
        __syncthreads();
    }
#pragma unroll
    for (int r = 0; r < 4; ++r) {
        int m = ty * 4 + r;
#pragma unroll
        for (int c = 0; c < 4; ++c) {
            g_gpart[((size_t)kc * GM + m) * H + n0 + tx * 4 + c] = acc[r][c];
        }
    }
}

// grid 124, block 256, float4
__global__ __launch_bounds__(256) void gemm_reduce(const float* __restrict__ bias) {
    int idx4 = blockIdx.x * 256 + threadIdx.x;
    if (idx4 >= NB * H / 4) return;
    int m = idx4 / (H / 4), n4 = idx4 % (H / 4);
    const float4* __restrict__ gp4 = (const float4*)g_gpart;
    float4 s = make_float4(0.f, 0.f, 0.f, 0.f);
#pragma unroll
    for (int kc = 0; kc < KCH; ++kc) {
        float4 v = gp4[((size_t)kc * GM + m) * (H / 4) + n4];
        s.x += v.x; s.y += v.y; s.z += v.z; s.w += v.w;
    }
    float4 b = ((const float4*)bias)[n4];
    float4 o;
    o.x = selu_f(s.x + b.x); o.y = selu_f(s.y + b.y);
    o.z = selu_f(s.z + b.z); o.w = selu_f(s.w + b.w);
    ((float4*)g_hX2)[idx4] = o;
}

// ---------------- stage layer3 partials: grid (62, 16), block 128 --------
// Block (m, kc): covers k in [kc*128, kc*128+128), split into 2 halves of 64.
__global__ __launch_bounds__(128) void l3_part(const float* __restrict__ W3) {
    __shared__ float sh[128];
    int m = blockIdx.x;
    int kc = blockIdx.y;
    int t = threadIdx.x;
    sh[t] = g_hX2[m * H + kc * 128 + t];
    __syncthreads();
    int n = t & 63, half = t >> 6;
    float acc = 0.f;
    if (n < P) {
        int kb = kc * 128 + half * 64;
        int ks = half * 64;
#pragma unroll 8
        for (int k = 0; k < 64; ++k) acc += sh[ks + k] * W3[(kb + k) * P + n];
    }
    g_l3p[((size_t)m * 32 + kc * 2 + half) * 64 + n] = acc;
}

// fused: reduce 32 partials + bias + softmax + scale. grid 62, block 64
__global__ __launch_bounds__(64) void l3_fused(const float* __restrict__ b3, int stage) {
    __shared__ float vals[64];
    __shared__ float red;
    int m = blockIdx.x, t = threadIdx.x;
    float s = 0.f;
#pragma unroll 8
    for (int c = 0; c < 32; ++c) s += g_l3p[((size_t)m * 32 + c) * 64 + t];
    float v = (t < P) ? (s + b3[t]) : -1e30f;
    vals[t] = v;
    __syncthreads();
    if (t == 0) { float mx = -1e30f; for (int i = 0; i < P; ++i) mx = fmaxf(mx, vals[i]); red = mx; }
    __syncthreads();
    float e = (t < P) ? expf(v - red) : 0.f;
    vals[t] = e;
    __syncthreads();
    if (t == 0) { float ss = 0.f; for (int i = 0; i < P; ++i) ss += vals[i]; red = ss; }
    __syncthreads();
    float scale = (stage == 0) ? g_probs1[m] : g_probs2[m];
    if (t < P) g_flat[m * P + t] = (e / red) * scale;
}

// ---------------- exact top-62 of 3844 by rank count ---------------------
// grid 61, block 256 = 64 g-values x 4 scan segments (241/240/240/240 float4)
__global__ __launch_bounds__(256) void topk62(int stage, float* __restrict__ out) {
    __shared__ float sv[NBP];        // 3844 floats
    __shared__ int   pr[4][64];
    int t = threadIdx.x;
    float4* sv4s = (float4*)sv;
    const float4* gf4 = (const float4*)g_flat;
    for (int i = t; i < NBP / 4; i += 256) sv4s[i] = gf4[i];
    __syncthreads();
    int gl = t & 63, seg = t >> 6;
    int g = blockIdx.x * 64 + gl;
    float v = (g < NBP) ? sv[g] : 0.f;
    int q0 = (seg == 0) ? 0 : (241 + (seg - 1) * 240);
    int qn = (seg == 0) ? 241 : 240;
    int r = 0;
    const float4* sv4 = (const float4*)sv;
#pragma unroll 4
    for (int qq = 0; qq < qn; ++qq) {
        int q = q0 + qq;
        float4 o = sv4[q];
        int base = q * 4;
        r += (o.x > v) || (o.x == v && (base + 0) < g);
        r += (o.y > v) || (o.y == v && (base + 1) < g);
        r += (o.z > v) || (o.z == v && (base + 2) < g);
        r += (o.w > v) || (o.w == v && (base + 3) < g);
    }
    pr[seg][gl] = r;
    __syncthreads();
    if (seg == 0 && g < NBP) {
        int rt = pr[0][gl] + pr[1][gl] + pr[2][gl] + pr[3][gl];
        if (rt < NB) {
            int row = g / P, col = g % P;
            if (stage == 0) {
                g_probs2[rt] = v;
                g_pb2[rt] = g_pitch1[row];
                g_pa2[rt] = col;
            } else {
                out[rt * 4 + 0] = v;
                out[rt * 4 + 1] = (float)g_pb2[row];
                out[rt * 4 + 2] = (float)g_pa2[row];
                out[rt * 4 + 3] = (float)col;
            }
        }
    }
}

// ---------------- launch ---------------------------------------------------
extern "C" void kernel_launch(void* const* d_in, const int* in_sizes, int n_in,
                              void* d_out, int out_size) {
    (void)in_sizes; (void)n_in; (void)out_size;
    const float* x   = (const float*)d_in[0];
    const float* bw1 = (const float*)d_in[1];
    const float* bb1 = (const float*)d_in[2];
    const float* bw2 = (const float*)d_in[3];
    const float* bb2 = (const float*)d_in[4];
    const float* bw3 = (const float*)d_in[5];
    const float* bb3 = (const float*)d_in[6];
    const float* aw1 = (const float*)d_in[7];
    const float* ab1 = (const float*)d_in[8];
    const float* aw2 = (const float*)d_in[9];
    const float* ab2 = (const float*)d_in[10];
    const float* aw3 = (const float*)d_in[11];
    const float* ab3 = (const float*)d_in[12];
    const float* tw1 = (const float*)d_in[13];
    const float* tb1 = (const float*)d_in[14];
    const float* tw2 = (const float*)d_in[15];
    const float* tb2 = (const float*)d_in[16];
    const float* tw3 = (const float*)d_in[17];
    const float* tb3 = (const float*)d_in[18];
    float* out = (float*)d_out;

    big_matvec<<<dim3(H / 512, DCH, 3), 128>>>(x, bw1, aw1, tw1);
    big_reduce<<<dim3(H / 512, 3), 512>>>(bb1, ab1, tb1);

    // bass trunk
    l2_part<<<dim3(H / 512, 64), 128>>>(bw2);
    l2_reduce<<<H / 512, 512>>>(bb2);
    bass_l3_part<<<32, 64>>>(bw3);
    bass_fused<<<1, 64>>>(bb3);

    // alto stage
    hidden1<<<dim3(H / 512, NB), 128>>>(0, aw1);
    gemm_part<<<dim3(32, KCH), 256>>>(aw2);
    gemm_reduce<<<124, 256>>>(ab2);
    l3_part<<<dim3(NB, 16), 128>>>(aw3);
    l3_fused<<<NB, 64>>>(ab3, 0);
    topk62<<<61, 256>>>(0, out);

    // tenor stage
    hidden1<<<dim3(H / 512, NB), 128>>>(1, tw1);
    gemm_part<<<dim3(32, KCH), 256>>>(tw2);
    gemm_reduce<<<124, 256>>>(tb2);
    l3_part<<<dim3(NB, 16), 128>>>(tw3);
    l3_fused<<<NB, 64>>>(tb3, 1);
    topk62<<<61, 256>>>(1, out);
}

// round 6
// speedup vs baseline: 1.7937x; 1.0616x over previous
#include <cuda_runtime.h>
#include <math.h>
#include <stdint.h>

#define D   10112
#define H   2048
#define P   62
#define NB  62
#define NBP (NB*P)     // 3844
#define DCH 79         // D / 128

// ---------------- scratch (device globals; no allocation) ----------------
__device__ float g_bigpart[3 * DCH * H];   // split-K partials for the 3 big matvecs
__device__ float g_h1[H];                  // bass hidden1 (post-selu)
__device__ float g_ua0[H];                 // alto  x@aw1[:D] + ab1 (pre-selu, shared part)
__device__ float g_ut0[H];                 // tenor x@tw1[:D] + tb1
__device__ float g_p2[64 * H];             // bass layer2 partials (64 k-chunks)
__device__ float g_h2[H];                  // bass hidden2
__device__ float g_lbp[16 * 64];           // bass layer3 partials
__device__ float g_probs1[NB];             // bass probs sorted desc
__device__ int   g_pitch1[NB];             // bass pitches sorted by prob
__device__ float g_hX1[NB * H];            // stage hidden1 (62 x 2048)
__device__ float g_gpart[8 * 64 * H];      // GEMM split-K partials
__device__ float g_hX2[NB * H];            // stage hidden2
__device__ float g_l3p[62 * 16 * 64];      // stage L3 partials
__device__ float g_flat[NBP];              // softmax*prob flattened
__device__ float g_probs2[NB];
__device__ int   g_pb2[NB];
__device__ int   g_pa2[NB];

__device__ __forceinline__ float selu_f(float x) {
    const float sc = 1.0507009873554805f;
    const float al = 1.6732632423543772f;
    return x > 0.f ? sc * x : sc * al * expm1f(x);
}

// ---------------- big D->H matvec kernels, split-K ------------------------
// bass only: grid (4, 79), block 128
__global__ __launch_bounds__(128, 8) void big_matvec1(const float* __restrict__ x,
                                                      const float* __restrict__ W) {
    __shared__ float sx[128];
    int t = threadIdx.x;
    int j4 = blockIdx.x * 128 + t;
    int c = blockIdx.y;
    int i0 = c * 128;
    sx[t] = x[i0 + t];
    __syncthreads();
    const float4* __restrict__ W4 = (const float4*)W;
    float4 acc = make_float4(0.f, 0.f, 0.f, 0.f);
#pragma unroll 8
    for (int i = 0; i < 128; ++i) {
        float xv = sx[i];
        float4 w = W4[(size_t)(i0 + i) * (H / 4) + j4];
        acc.x += xv * w.x; acc.y += xv * w.y; acc.z += xv * w.z; acc.w += xv * w.w;
    }
    ((float4*)g_bigpart)[(size_t)c * (H / 4) + j4] = acc;
}

// alto+tenor: grid (4, 79, 2), block 128. z=0 -> aw1 (slot 1), z=1 -> tw1 (slot 2)
__global__ __launch_bounds__(128, 8) void big_matvec2(const float* __restrict__ x,
                                                      const float* __restrict__ Wa,
                                                      const float* __restrict__ Wt) {
    __shared__ float sx[128];
    int t = threadIdx.x;
    int j4 = blockIdx.x * 128 + t;
    int c = blockIdx.y;
    int z = blockIdx.z;
    const float* __restrict__ W = (z == 0) ? Wa : Wt;
    int i0 = c * 128;
    sx[t] = x[i0 + t];
    __syncthreads();
    const float4* __restrict__ W4 = (const float4*)W;
    float4 acc = make_float4(0.f, 0.f, 0.f, 0.f);
#pragma unroll 8
    for (int i = 0; i < 128; ++i) {
        float xv = sx[i];
        float4 w = W4[(size_t)(i0 + i) * (H / 4) + j4];
        acc.x += xv * w.x; acc.y += xv * w.y; acc.z += xv * w.z; acc.w += xv * w.w;
    }
    ((float4*)g_bigpart)[((size_t)(z + 1) * DCH + c) * (H / 4) + j4] = acc;
}

// bass reduce: grid 8, block 512 = 64 float4-cols x 8 chunk-groups (10..10,9)
__global__ __launch_bounds__(512) void big_reduce_bass(const float* __restrict__ bb1) {
    __shared__ float4 sred[8][64];
    int t = threadIdx.x;
    int col = t & 63;
    int grp = t >> 6;
    int j4 = blockIdx.x * 64 + col;
    const float4* __restrict__ bp4 = (const float4*)g_bigpart;
    int c0 = grp * 10;
    int cn = (grp == 7) ? 9 : 10;
    float4 s = make_float4(0.f, 0.f, 0.f, 0.f);
#pragma unroll 10
    for (int c = 0; c < cn; ++c) {
        float4 v = bp4[(size_t)(c0 + c) * (H / 4) + j4];
        s.x += v.x; s.y += v.y; s.z += v.z; s.w += v.w;
    }
    sred[grp][col] = s;
    __syncthreads();
    if (grp == 0) {
        float4 sm = sred[0][col];
#pragma unroll
        for (int g = 1; g < 8; ++g) {
            float4 v = sred[g][col];
            sm.x += v.x; sm.y += v.y; sm.z += v.z; sm.w += v.w;
        }
        float4 bb = ((const float4*)bb1)[j4];
        float4 o;
        o.x = selu_f(sm.x + bb.x); o.y = selu_f(sm.y + bb.y);
        o.z = selu_f(sm.z + bb.z); o.w = selu_f(sm.w + bb.w);
        ((float4*)g_h1)[j4] = o;
    }
}

// alto+tenor reduce: grid (8, 2), block 512
__global__ __launch_bounds__(512) void big_reduce_at(const float* __restrict__ ab1,
                                                     const float* __restrict__ tb1) {
    __shared__ float4 sred[8][64];
    int t = threadIdx.x;
    int col = t & 63;
    int grp = t >> 6;
    int j4 = blockIdx.x * 64 + col;
    int z = blockIdx.y;              // 0 -> alto (slot 1), 1 -> tenor (slot 2)
    const float4* __restrict__ bp4 = (const float4*)g_bigpart;
    int c0 = grp * 10;
    int cn = (grp == 7) ? 9 : 10;
    float4 s = make_float4(0.f, 0.f, 0.f, 0.f);
#pragma unroll 10
    for (int c = 0; c < cn; ++c) {
        float4 v = bp4[((size_t)(z + 1) * DCH + c0 + c) * (H / 4) + j4];
        s.x += v.x; s.y += v.y; s.z += v.z; s.w += v.w;
    }
    sred[grp][col] = s;
    __syncthreads();
    if (grp == 0) {
        float4 sm = sred[0][col];
#pragma unroll
        for (int g = 1; g < 8; ++g) {
            float4 v = sred[g][col];
            sm.x += v.x; sm.y += v.y; sm.z += v.z; sm.w += v.w;
        }
        if (z == 0) {
            float4 bb = ((const float4*)ab1)[j4];
            ((float4*)g_ua0)[j4] = make_float4(sm.x + bb.x, sm.y + bb.y, sm.z + bb.z, sm.w + bb.w);
        } else {
            float4 bb = ((const float4*)tb1)[j4];
            ((float4*)g_ut0)[j4] = make_float4(sm.x + bb.x, sm.y + bb.y, sm.z + bb.z, sm.w + bb.w);
        }
    }
}

// ---------------- bass layer2: 2048->2048 matvec, split-K (chunk 32) -----
// grid (4, 64), block 128
__global__ __launch_bounds__(128, 8) void l2_part(const float* __restrict__ W) {
    __shared__ float sx[32];
    int t = threadIdx.x;
    int j4 = blockIdx.x * 128 + t;
    int c = blockIdx.y;
    int i0 = c * 32;
    if (t < 32) sx[t] = g_h1[i0 + t];
    __syncthreads();
    const float4* __restrict__ W4 = (const float4*)W;
    float4 acc = make_float4(0.f, 0.f, 0.f, 0.f);
#pragma unroll 8
    for (int i = 0; i < 32; ++i) {
        float xv = sx[i];
        float4 w = W4[(size_t)(i0 + i) * (H / 4) + j4];
        acc.x += xv * w.x; acc.y += xv * w.y; acc.z += xv * w.z; acc.w += xv * w.w;
    }
    ((float4*)g_p2)[(size_t)c * (H / 4) + j4] = acc;
}

// grid 16, block 256 = 32 float4-cols x 8 groups of 8 chunks
__global__ __launch_bounds__(256) void l2_reduce(const float* __restrict__ b) {
    __shared__ float4 sred[8][32];
    int t = threadIdx.x;
    int col = t & 31;
    int grp = t >> 5;
    int j4 = blockIdx.x * 32 + col;
    const float4* __restrict__ p4 = (const float4*)g_p2;
    float4 s = make_float4(0.f, 0.f, 0.f, 0.f);
#pragma unroll
    for (int c = 0; c < 8; ++c) {
        float4 v = p4[(size_t)(grp * 8 + c) * (H / 4) + j4];
        s.x += v.x; s.y += v.y; s.z += v.z; s.w += v.w;
    }
    sred[grp][col] = s;
    __syncthreads();
    if (grp == 0) {
        float4 sm = sred[0][col];
#pragma unroll
        for (int g = 1; g < 8; ++g) {
            float4 v = sred[g][col];
            sm.x += v.x; sm.y += v.y; sm.z += v.z; sm.w += v.w;
        }
        float4 bv = ((const float4*)b)[j4];
        float4 o;
        o.x = selu_f(sm.x + bv.x); o.y = selu_f(sm.y + bv.y);
        o.z = selu_f(sm.z + bv.z); o.w = selu_f(sm.w + bv.w);
        ((float4*)g_h2)[j4] = o;
    }
}

// ---------------- bass layer3: 2048->62 ----------------------------------
// grid 16, block 256 = 64 n-lanes x 4 k-groups of 32
__global__ __launch_bounds__(256) void bass_l3_part(const float* __restrict__ W3) {
    __shared__ float sh[128];
    __shared__ float sred[4][64];
    int kc = blockIdx.x;
    int t = threadIdx.x;
    if (t < 128) sh[t] = g_h2[kc * 128 + t];
    __syncthreads();
    int n = t & 63, kg = t >> 6;
    float acc = 0.f;
    if (n < P) {
        int kb = kc * 128 + kg * 32;
        int ks = kg * 32;
#pragma unroll 8
        for (int k = 0; k < 32; ++k) acc += sh[ks + k] * W3[(kb + k) * P + n];
    }
    sred[kg][n] = acc;
    __syncthreads();
    if (kg == 0) {
        float s = ((sred[0][n] + sred[1][n]) + sred[2][n]) + sred[3][n];
        g_lbp[kc * 64 + n] = s;
    }
}

// fused: reduce partials + bias + softmax + descending sort. grid 1, block 64
__global__ __launch_bounds__(64) void bass_fused(const float* __restrict__ b3) {
    __shared__ float pv[64];
    __shared__ float red;
    int t = threadIdx.x;
    float s = 0.f;
#pragma unroll
    for (int c = 0; c < 16; ++c) s += g_lbp[c * 64 + t];
    float v = (t < P) ? (s + b3[t]) : -1e30f;
    pv[t] = v;
    __syncthreads();
    if (t == 0) { float mx = -1e30f; for (int i = 0; i < P; ++i) mx = fmaxf(mx, pv[i]); red = mx; }
    __syncthreads();
    float e = (t < P) ? expf(v - red) : 0.f;
    pv[t] = e;
    __syncthreads();
    if (t == 0) { float ss = 0.f; for (int i = 0; i < P; ++i) ss += pv[i]; red = ss; }
    __syncthreads();
    float p = e / red;
    pv[t] = (t < P) ? p : -1.f;
    __syncthreads();
    if (t < P) {
        int r = 0;
        for (int i = 0; i < P; ++i) {
            float o = pv[i];
            r += (o > p) || (o == p && i < t);
        }
        g_probs1[r] = p;
        g_pitch1[r] = t;
    }
}

// ---------------- stage hidden1 via row-gather + selu --------------------
// grid (4, 62), block 128, float4
__global__ __launch_bounds__(128) void hidden1(int stage, const float* __restrict__ W1) {
    int j4 = blockIdx.x * 128 + threadIdx.x;
    int i = blockIdx.y;
    const float4* __restrict__ W4 = (const float4*)W1;
    float4 o;
    if (stage == 0) {
        int pb = g_pitch1[i];
        float4 u = ((const float4*)g_ua0)[j4];
        float4 w = W4[(size_t)(D + pb) * (H / 4) + j4];
        o = make_float4(u.x + w.x, u.y + w.y, u.z + w.z, u.w + w.w);
    } else {
        int pb = g_pb2[i];
        int pa = g_pa2[i];
        float4 u = ((const float4*)g_ut0)[j4];
        float4 wb = W4[(size_t)(D + pb) * (H / 4) + j4];
        float4 wa = W4[(size_t)(D + P + pa) * (H / 4) + j4];
        o = make_float4(u.x + wb.x + wa.x, u.y + wb.y + wa.y,
                        u.z + wb.z + wa.z, u.w + wb.w + wa.w);
    }
    float4 r;
    r.x = selu_f(o.x); r.y = selu_f(o.y); r.z = selu_f(o.z); r.w = selu_f(o.w);
    ((float4*)g_hX1)[(size_t)i * (H / 4) + j4] = r;
}

// ---------------- stage layer2 GEMM: (62x2048) @ (2048x2048), split-K ----
#define GM  64
#define GN  64
#define GKT 32
#define KCH 8
#define KLEN (H / KCH)   // 256
__global__ __launch_bounds__(256) void gemm_part(const float* __restrict__ B) {
    __shared__ float sA[GKT][GM + 1];
    __shared__ float sB[GKT][GN];
    int t = threadIdx.x;
    int n0 = blockIdx.x * GN;
    int kc = blockIdx.y;
    int kbase = kc * KLEN;
    int tx = t & 15, ty = t >> 4;
    float acc[4][4] = {};
    for (int kt = 0; kt < KLEN; kt += GKT) {
        int k0 = kbase + kt;
#pragma unroll
        for (int r = 0; r < 8; ++r) {
            int idx = t + r * 256;
            int kk = idx & 31, mm = idx >> 5;
            sA[kk][mm] = (mm < NB) ? g_hX1[mm * H + k0 + kk] : 0.f;
        }
#pragma unroll
        for (int r = 0; r < 8; ++r) {
            int idx = t + r * 256;
            int nn = idx & 63, kk = idx >> 6;
            sB[kk][nn] = B[(size_t)(k0 + kk) * H + n0 + nn];
        }
        __syncthreads();
#pragma unroll
        for (int k = 0; k < GKT; ++k) {
            float a[4], b[4];
#pragma unroll
            for (int r = 0; r < 4; ++r) a[r] = sA[k][ty * 4 + r];
#pragma unroll
            for (int c = 0; c < 4; ++c) b[c] = sB[k][tx * 4 + c];
#pragma unroll
            for (int r = 0; r < 4; ++r)
#pragma unroll
                for (int c = 0; c < 4; ++c) acc[r][c] += a[r] * b[c];
        }
        __syncthreads();
    }
#pragma unroll
    for (int r = 0; r < 4; ++r) {
        int m = ty * 4 + r;
#pragma unroll
        for (int c = 0; c < 4; ++c) {
            g_gpart[((size_t)kc * GM + m) * H + n0 + tx * 4 + c] = acc[r][c];
        }
    }
}

// grid 124, block 256, float4
__global__ __launch_bounds__(256) void gemm_reduce(const float* __restrict__ bias) {
    int idx4 = blockIdx.x * 256 + threadIdx.x;
    if (idx4 >= NB * H / 4) return;
    int m = idx4 / (H / 4), n4 = idx4 % (H / 4);
    const float4* __restrict__ gp4 = (const float4*)g_gpart;
    float4 s = make_float4(0.f, 0.f, 0.f, 0.f);
#pragma unroll
    for (int kc = 0; kc < KCH; ++kc) {
        float4 v = gp4[((size_t)kc * GM + m) * (H / 4) + n4];
        s.x += v.x; s.y += v.y; s.z += v.z; s.w += v.w;
    }
    float4 b = ((const float4*)bias)[n4];
    float4 o;
    o.x = selu_f(s.x + b.x); o.y = selu_f(s.y + b.y);
    o.z = selu_f(s.z + b.z); o.w = selu_f(s.w + b.w);
    ((float4*)g_hX2)[idx4] = o;
}

// ---------------- stage layer3 partials: grid (62, 16), block 256 --------
__global__ __launch_bounds__(256) void l3_part(const float* __restrict__ W3) {
    __shared__ float sh[128];
    __shared__ float sred[4][64];
    int m = blockIdx.x;
    int kc = blockIdx.y;
    int t = threadIdx.x;
    if (t < 128) sh[t] = g_hX2[m * H + kc * 128 + t];
    __syncthreads();
    int n = t & 63, kg = t >> 6;
    float acc = 0.f;
    if (n < P) {
        int kb = kc * 128 + kg * 32;
        int ks = kg * 32;
#pragma unroll 8
        for (int k = 0; k < 32; ++k) acc += sh[ks + k] * W3[(kb + k) * P + n];
    }
    sred[kg][n] = acc;
    __syncthreads();
    if (kg == 0) {
        float s = ((sred[0][n] + sred[1][n]) + sred[2][n]) + sred[3][n];
        g_l3p[((size_t)m * 16 + kc) * 64 + n] = s;
    }
}

// fused: reduce 16 partials + bias + softmax + scale. grid 62, block 64
__global__ __launch_bounds__(64) void l3_fused(const float* __restrict__ b3, int stage) {
    __shared__ float vals[64];
    __shared__ float red;
    int m = blockIdx.x, t = threadIdx.x;
    float s = 0.f;
#pragma unroll
    for (int c = 0; c < 16; ++c) s += g_l3p[((size_t)m * 16 + c) * 64 + t];
    float v = (t < P) ? (s + b3[t]) : -1e30f;
    vals[t] = v;
    __syncthreads();
    if (t == 0) { float mx = -1e30f; for (int i = 0; i < P; ++i) mx = fmaxf(mx, vals[i]); red = mx; }
    __syncthreads();
    float e = (t < P) ? expf(v - red) : 0.f;
    vals[t] = e;
    __syncthreads();
    if (t == 0) { float ss = 0.f; for (int i = 0; i < P; ++i) ss += vals[i]; red = ss; }
    __syncthreads();
    float scale = (stage == 0) ? g_probs1[m] : g_probs2[m];
    if (t < P) g_flat[m * P + t] = (e / red) * scale;
}

// ---------------- exact top-62 of 3844 by rank count ---------------------
// grid 61, block 512 = 64 g-values x 8 scan segments (121/120x7 float4)
__global__ __launch_bounds__(512) void topk62(int stage, float* __restrict__ out) {
    __shared__ float sv[NBP];        // 3844 floats
    __shared__ int   pr[8][64];
    int t = threadIdx.x;
    float4* sv4s = (float4*)sv;
    const float4* gf4 = (const float4*)g_flat;
    for (int i = t; i < NBP / 4; i += 512) sv4s[i] = gf4[i];
    __syncthreads();
    int gl = t & 63, seg = t >> 6;
    int g = blockIdx.x * 64 + gl;
    float v = (g < NBP) ? sv[g] : 0.f;
    int q0 = (seg == 0) ? 0 : (121 + (seg - 1) * 120);
    int qn = (seg == 0) ? 121 : 120;
    int r = 0;
    const float4* sv4 = (const float4*)sv;
#pragma unroll 4
    for (int qq = 0; qq < qn; ++qq) {
        int q = q0 + qq;
        float4 o = sv4[q];
        int base = q * 4;
        r += (o.x > v) || (o.x == v && (base + 0) < g);
        r += (o.y > v) || (o.y == v && (base + 1) < g);
        r += (o.z > v) || (o.z == v && (base + 2) < g);
        r += (o.w > v) || (o.w == v && (base + 3) < g);
    }
    pr[seg][gl] = r;
    __syncthreads();
    if (seg == 0 && g < NBP) {
        int rt = 0;
#pragma unroll
        for (int q = 0; q < 8; ++q) rt += pr[q][gl];
        if (rt < NB) {
            int row = g / P, col = g % P;
            if (stage == 0) {
                g_probs2[rt] = v;
                g_pb2[rt] = g_pitch1[row];
                g_pa2[rt] = col;
            } else {
                out[rt * 4 + 0] = v;
                out[rt * 4 + 1] = (float)g_pb2[row];
                out[rt * 4 + 2] = (float)g_pa2[row];
                out[rt * 4 + 3] = (float)col;
            }
        }
    }
}

// ---------------- launch ---------------------------------------------------
extern "C" void kernel_launch(void* const* d_in, const int* in_sizes, int n_in,
                              void* d_out, int out_size) {
    (void)in_sizes; (void)n_in; (void)out_size;
    const float* x   = (const float*)d_in[0];
    const float* bw1 = (const float*)d_in[1];
    const float* bb1 = (const float*)d_in[2];
    const float* bw2 = (const float*)d_in[3];
    const float* bb2 = (const float*)d_in[4];
    const float* bw3 = (const float*)d_in[5];
    const float* bb3 = (const float*)d_in[6];
    const float* aw1 = (const float*)d_in[7];
    const float* ab1 = (const float*)d_in[8];
    const float* aw2 = (const float*)d_in[9];
    const float* ab2 = (const float*)d_in[10];
    const float* aw3 = (const float*)d_in[11];
    const float* ab3 = (const float*)d_in[12];
    const float* tw1 = (const float*)d_in[13];
    const float* tb1 = (const float*)d_in[14];
    const float* tw2 = (const float*)d_in[15];
    const float* tb2 = (const float*)d_in[16];
    const float* tw3 = (const float*)d_in[17];
    const float* tb3 = (const float*)d_in[18];
    float* out = (float*)d_out;

    // fork-join resources: host-side only (no device memory). Created once,
    // outside any capture (first call is the uncaptured correctness run),
    // reused on every subsequent call -> identical work every call.
    static cudaStream_t s1 = nullptr;
    static cudaEvent_t e1 = nullptr, e2 = nullptr;
    if (s1 == nullptr) {
        cudaStreamCreateWithFlags(&s1, cudaStreamNonBlocking);
        cudaEventCreateWithFlags(&e1, cudaEventDisableTiming);
        cudaEventCreateWithFlags(&e2, cudaEventDisableTiming);
    }

    // fork: side stream does the alto/tenor big matvecs (pure BW) while the
    // main stream runs the latency-bound bass trunk.
    cudaEventRecord(e1, 0);
    cudaStreamWaitEvent(s1, e1, 0);
    big_matvec2<<<dim3(4, DCH, 2), 128, 0, s1>>>(x, aw1, tw1);
    big_reduce_at<<<dim3(8, 2), 512, 0, s1>>>(ab1, tb1);
    cudaEventRecord(e2, s1);

    // bass trunk on the main (capture) stream
    big_matvec1<<<dim3(4, DCH), 128>>>(x, bw1);
    big_reduce_bass<<<8, 512>>>(bb1);
    l2_part<<<dim3(4, 64), 128>>>(bw2);
    l2_reduce<<<16, 256>>>(bb2);
    bass_l3_part<<<16, 256>>>(bw3);
    bass_fused<<<1, 64>>>(bb3);

    cudaStreamWaitEvent(0, e2, 0);   // join: need g_ua0/g_ut0 from s1

    // alto stage
    hidden1<<<dim3(4, NB), 128>>>(0, aw1);
    gemm_part<<<dim3(32, KCH), 256>>>(aw2);
    gemm_reduce<<<124, 256>>>(ab2);
    l3_part<<<dim3(NB, 16), 256>>>(aw3);
    l3_fused<<<NB, 64>>>(ab3, 0);
    topk62<<<61, 512>>>(0, out);

    // tenor stage
    hidden1<<<dim3(4, NB), 128>>>(1, tw1);
    gemm_part<<<dim3(32, KCH), 256>>>(tw2);
    gemm_reduce<<<124, 256>>>(tb2);
    l3_part<<<dim3(NB, 16), 256>>>(tw3);
    l3_fused<<<NB, 64>>>(tb3, 1);
    topk62<<<61, 512>>>(1, out);
}